// round 1
// baseline (speedup 1.0000x reference)
#include <cuda_runtime.h>
#include <math.h>

#define Nn 50000
#define Ee 300000
#define Dd 256
#define Ff 1024
#define Cc 40

// ---------------- device scratch (static; no allocation) ----------------
__device__ float g_X[Nn * Dd];
__device__ float g_M[Nn * Dd];
__device__ float g_Y[Nn * Dd];
__device__ float g_norm_s[Nn];
__device__ float g_norm_d[Nn];
__device__ int   g_deg_out[Nn];
__device__ int   g_deg_in[Nn];
__device__ int   g_row_ptr[Nn + 1];
__device__ int   g_fill[Nn];
__device__ int   g_col[Ee];
__device__ float g_bn_sum[Dd];
__device__ float g_bn_sq[Dd];
__device__ float g_bn_scale[Dd];
__device__ float g_bn_shift[Dd];

// ---------------- init ----------------
__global__ void k_zero_init() {
    int i = blockIdx.x * blockDim.x + threadIdx.x;
    if (i < Nn) {
        g_deg_out[i] = 0;
        g_deg_in[i] = 0;
        g_fill[i] = 0;
    }
    if (i < Dd) {
        g_bn_sum[i] = 0.f;
        g_bn_sq[i] = 0.f;
    }
}

__global__ void k_degrees(const int* __restrict__ src, const int* __restrict__ dst) {
    int e = blockIdx.x * blockDim.x + threadIdx.x;
    if (e >= Ee) return;
    atomicAdd(&g_deg_out[src[e]], 1);
    atomicAdd(&g_deg_in[dst[e]], 1);
}

__global__ void k_norms() {
    int i = blockIdx.x * blockDim.x + threadIdx.x;
    if (i >= Nn) return;
    int dو = g_deg_out[i]; if (dو < 1) dو = 1;
    int di = g_deg_in[i];  if (di < 1) di = 1;
    g_norm_s[i] = rsqrtf((float)dو);
    g_norm_d[i] = rsqrtf((float)di);
}

// single-block exclusive scan of in-degrees -> row_ptr
__global__ void k_rowptr() {
    __shared__ int sh[1024];
    const int tid = threadIdx.x;
    const int CH = (Nn + 1023) / 1024;
    int beg = tid * CH;
    int end = beg + CH; if (end > Nn) end = Nn;
    int s = 0;
    for (int i = beg; i < end; i++) s += g_deg_in[i];
    sh[tid] = s;
    __syncthreads();
    for (int off = 1; off < 1024; off <<= 1) {
        int v = (tid >= off) ? sh[tid - off] : 0;
        __syncthreads();
        sh[tid] += v;
        __syncthreads();
    }
    int run = sh[tid] - s;   // exclusive prefix
    for (int i = beg; i < end; i++) {
        g_row_ptr[i] = run;
        run += g_deg_in[i];
    }
    if (tid == 0) g_row_ptr[Nn] = Ee;
}

__global__ void k_fill(const int* __restrict__ src, const int* __restrict__ dst) {
    int e = blockIdx.x * blockDim.x + threadIdx.x;
    if (e >= Ee) return;
    int d = dst[e];
    int p = g_row_ptr[d] + atomicAdd(&g_fill[d], 1);
    g_col[p] = src[e];
}

// ---------------- SpMM gather: M[v] = norm_d[v] * sum_{e:dst=v} norm_s[src]*X[src] ----------------
__global__ void k_gather(const float* __restrict__ X, float* __restrict__ Mo) {
    int w = (blockIdx.x * blockDim.x + threadIdx.x) >> 5;
    int lane = threadIdx.x & 31;
    if (w >= Nn) return;
    int beg = g_row_ptr[w], end = g_row_ptr[w + 1];
    float4 a0 = make_float4(0.f, 0.f, 0.f, 0.f);
    float4 a1 = make_float4(0.f, 0.f, 0.f, 0.f);
    for (int e = beg; e < end; e++) {
        int s = g_col[e];
        float wt = g_norm_s[s];
        const float4* r = (const float4*)(X + (size_t)s * Dd);
        float4 v0 = r[lane];
        float4 v1 = r[lane + 32];
        a0.x += wt * v0.x; a0.y += wt * v0.y; a0.z += wt * v0.z; a0.w += wt * v0.w;
        a1.x += wt * v1.x; a1.y += wt * v1.y; a1.z += wt * v1.z; a1.w += wt * v1.w;
    }
    float wd = g_norm_d[w];
    a0.x *= wd; a0.y *= wd; a0.z *= wd; a0.w *= wd;
    a1.x *= wd; a1.y *= wd; a1.z *= wd; a1.w *= wd;
    float4* o = (float4*)(Mo + (size_t)w * Dd);
    o[lane] = a0;
    o[lane + 32] = a1;
}

// ---------------- SGEMM: C[M,Nc] = A[M,K] @ B[K,Nc] + bias ----------------
#define BM 128
#define BN 128
#define BK 8
#define TM 8
#define TN 8

__global__ __launch_bounds__(256) void sgemm_bias(
    const float* __restrict__ A, const float* __restrict__ B,
    const float* __restrict__ bias, float* __restrict__ C,
    int M, int K, int Nc)
{
    __shared__ float As[BK][BM];
    __shared__ float Bs[BK][BN];
    const int tid = threadIdx.x;
    const int tx = tid & 15;       // 0..15  -> col group
    const int ty = tid >> 4;       // 0..15  -> row group
    const int rowBase = blockIdx.y * BM;
    const int colBase = blockIdx.x * BN;

    // A tile loader: 128 rows x 8 cols = 256 float4 (2 per row)
    const int aRow = tid >> 1;
    const int aCol = (tid & 1) * 4;
    // B tile loader: 8 rows x 128 cols = 256 float4
    const int bRow = tid >> 5;
    const int bCol = (tid & 31) * 4;

    float acc[TM][TN];
#pragma unroll
    for (int i = 0; i < TM; i++)
#pragma unroll
        for (int j = 0; j < TN; j++) acc[i][j] = 0.f;

    for (int k0 = 0; k0 < K; k0 += BK) {
        // load A tile (guard rows)
        float4 av = make_float4(0.f, 0.f, 0.f, 0.f);
        int gr = rowBase + aRow;
        if (gr < M) av = *(const float4*)(A + (size_t)gr * K + k0 + aCol);
        As[aCol + 0][aRow] = av.x;
        As[aCol + 1][aRow] = av.y;
        As[aCol + 2][aRow] = av.z;
        As[aCol + 3][aRow] = av.w;
        // load B tile (guard cols)
        float4 bv;
        const float* Brow = B + (size_t)(k0 + bRow) * Nc;
        int gc = colBase + bCol;
        if (gc + 3 < Nc) {
            bv = *(const float4*)(Brow + gc);
        } else {
            bv.x = (gc + 0 < Nc) ? Brow[gc + 0] : 0.f;
            bv.y = (gc + 1 < Nc) ? Brow[gc + 1] : 0.f;
            bv.z = (gc + 2 < Nc) ? Brow[gc + 2] : 0.f;
            bv.w = (gc + 3 < Nc) ? Brow[gc + 3] : 0.f;
        }
        *(float4*)&Bs[bRow][bCol] = bv;
        __syncthreads();

#pragma unroll
        for (int kk = 0; kk < BK; kk++) {
            float a[TM], b[TN];
#pragma unroll
            for (int i = 0; i < TM; i++) a[i] = As[kk][ty * TM + i];
#pragma unroll
            for (int j = 0; j < TN; j++) b[j] = Bs[kk][tx * TN + j];
#pragma unroll
            for (int i = 0; i < TM; i++)
#pragma unroll
                for (int j = 0; j < TN; j++) acc[i][j] += a[i] * b[j];
        }
        __syncthreads();
    }

#pragma unroll
    for (int i = 0; i < TM; i++) {
        int r = rowBase + ty * TM + i;
        if (r >= M) continue;
#pragma unroll
        for (int j = 0; j < TN; j++) {
            int c = colBase + tx * TN + j;
            if (c < Nc) C[(size_t)r * Nc + c] = acc[i][j] + bias[c];
        }
    }
}

// ---------------- batchnorm ----------------
#define BN_BLOCKS 200
#define BN_ROWS 250

__global__ void k_bn_stats(const float* __restrict__ X) {
    int c = threadIdx.x;           // 256 threads == Dd columns
    int r0 = blockIdx.x * BN_ROWS;
    float s = 0.f, q = 0.f;
    for (int i = 0; i < BN_ROWS; i++) {
        int r = r0 + i;
        if (r < Nn) {
            float v = X[(size_t)r * Dd + c];
            s += v;
            q += v * v;
        }
    }
    atomicAdd(&g_bn_sum[c], s);
    atomicAdd(&g_bn_sq[c], q);
}

__global__ void k_bn_finalize(const float* __restrict__ gamma, const float* __restrict__ beta) {
    int c = threadIdx.x;
    if (c >= Dd) return;
    float mu = g_bn_sum[c] / (float)Nn;
    float var = g_bn_sq[c] / (float)Nn - mu * mu;
    float inv = rsqrtf(var + 1e-5f);
    float sc = gamma[c] * inv;
    g_bn_scale[c] = sc;
    g_bn_shift[c] = beta[c] - mu * sc;
    // reset accumulators for the next BN pass (keeps launch deterministic)
    g_bn_sum[c] = 0.f;
    g_bn_sq[c] = 0.f;
}

__global__ void k_bn_apply_elu(float* __restrict__ X) {
    int i = blockIdx.x * blockDim.x + threadIdx.x;
    if (i >= Nn * Dd) return;
    int c = i & (Dd - 1);
    float y = g_bn_scale[c] * X[i] + g_bn_shift[c];
    X[i] = (y > 0.f) ? y : expm1f(y);
}

// ---------------- host orchestration ----------------
extern "C" void kernel_launch(void* const* d_in, const int* in_sizes, int n_in,
                              void* d_out, int out_size)
{
    const float* feat  = (const float*)d_in[0];
    const int*   src   = (const int*)d_in[1];
    const int*   dst   = (const int*)d_in[2];
    const float* W_fc  = (const float*)d_in[3];
    const float* b_fc  = (const float*)d_in[4];
    const float* W1    = (const float*)d_in[5];
    const float* b1    = (const float*)d_in[6];
    const float* W2    = (const float*)d_in[7];
    const float* b2    = (const float*)d_in[8];
    const float* W3    = (const float*)d_in[9];
    const float* b3    = (const float*)d_in[10];
    const float* gamma = (const float*)d_in[11];
    const float* beta  = (const float*)d_in[12];
    const float* W_lin = (const float*)d_in[13];
    const float* b_lin = (const float*)d_in[14];
    float* out = (float*)d_out;

    float *pX, *pM, *pY;
    cudaGetSymbolAddress((void**)&pX, g_X);
    cudaGetSymbolAddress((void**)&pM, g_M);
    cudaGetSymbolAddress((void**)&pY, g_Y);

    const int T = 256;

    // graph preprocessing
    k_zero_init<<<(Nn + T - 1) / T, T>>>();
    k_degrees<<<(Ee + T - 1) / T, T>>>(src, dst);
    k_norms<<<(Nn + T - 1) / T, T>>>();
    k_rowptr<<<1, 1024>>>();
    k_fill<<<(Ee + T - 1) / T, T>>>(src, dst);

    dim3 gemmGridD((Dd + BN - 1) / BN, (Nn + BM - 1) / BM); // (2, 391)
    dim3 gemmGridC((Cc + BN - 1) / BN, (Nn + BM - 1) / BM); // (1, 391)
    int gatherBlocks = (Nn * 32 + T - 1) / T;
    int ewBlocks = (Nn * Dd + T - 1) / T;

    // x = feat @ W_fc + b_fc
    sgemm_bias<<<gemmGridD, 256>>>(feat, W_fc, b_fc, pX, Nn, Ff, Dd);

    // layer 1
    k_gather<<<gatherBlocks, T>>>(pX, pM);
    sgemm_bias<<<gemmGridD, 256>>>(pM, W1, b1, pY, Nn, Dd, Dd);
    k_bn_stats<<<BN_BLOCKS, Dd>>>(pY);
    k_bn_finalize<<<1, Dd>>>(gamma, beta);
    k_bn_apply_elu<<<ewBlocks, T>>>(pY);

    // layer 2
    k_gather<<<gatherBlocks, T>>>(pY, pM);
    sgemm_bias<<<gemmGridD, 256>>>(pM, W2, b2, pX, Nn, Dd, Dd);
    k_bn_stats<<<BN_BLOCKS, Dd>>>(pX);
    k_bn_finalize<<<1, Dd>>>(gamma, beta);
    k_bn_apply_elu<<<ewBlocks, T>>>(pX);

    // layer 3 -> writes node embeddings straight into output
    k_gather<<<gatherBlocks, T>>>(pX, pM);
    sgemm_bias<<<gemmGridD, 256>>>(pM, W3, b3, out, Nn, Dd, Dd);

    // logits = x @ W_lin + b_lin -> second segment of output
    sgemm_bias<<<gemmGridC, 256>>>(out, W_lin, b_lin, out + (size_t)Nn * Dd, Nn, Dd, Cc);
}

// round 5
// speedup vs baseline: 1.4510x; 1.4510x over previous
#include <cuda_runtime.h>
#include <cstdint>
#include <math.h>

#define Nn 50000
#define Ee 300000
#define Dd 256
#define Ff 1024
#define Cc 40

// ---------------- device scratch (static; no allocation) ----------------
__device__ float g_X[Nn * Dd];
__device__ float g_M[Nn * Dd];
__device__ float g_Y[Nn * Dd];
__device__ float g_WtFc[Dd * Ff];   // W_fc^T  [256,1024]
__device__ float g_Wt1[Dd * Dd];
__device__ float g_Wt2[Dd * Dd];
__device__ float g_Wt3[Dd * Dd];
__device__ float g_norm_s[Nn];
__device__ float g_norm_d[Nn];
__device__ int   g_deg_out[Nn];
__device__ int   g_deg_in[Nn];
__device__ int   g_row_ptr[Nn + 1];
__device__ int   g_fill[Nn];
__device__ int   g_col[Ee];
__device__ int   g_bsum[256];
__device__ int   g_boff[256];
__device__ float g_bn_sum[Dd];
__device__ float g_bn_sq[Dd];
__device__ float g_bn_scale[Dd];
__device__ float g_bn_shift[Dd];

// ---------------- small helpers ----------------
static __device__ __forceinline__ uint32_t smem_u32(const void* p) {
    uint32_t a;
    asm("{ .reg .u64 t; cvta.to.shared.u64 t, %1; cvt.u32.u64 %0, t; }" : "=r"(a) : "l"(p));
    return a;
}
static __device__ __forceinline__ float tf32r(float v) {
    uint32_t u;
    asm("cvt.rna.tf32.f32 %0, %1;" : "=r"(u) : "f"(v));
    return __uint_as_float(u);
}
static __device__ __forceinline__ uint32_t tf32u(uint32_t x) {
    uint32_t r;
    asm("cvt.rna.tf32.f32 %0, %1;" : "=r"(r) : "f"(__uint_as_float(x)));
    return r;
}
static __device__ __forceinline__ void cp_async16(uint32_t dst, const void* src, int szn) {
    asm volatile("cp.async.cg.shared.global [%0], [%1], 16, %2;" :: "r"(dst), "l"(src), "r"(szn));
}
static __device__ __forceinline__ void ldsm4(uint32_t& r0, uint32_t& r1, uint32_t& r2, uint32_t& r3, uint32_t addr) {
    asm volatile("ldmatrix.sync.aligned.m8n8.x4.shared.b16 {%0,%1,%2,%3}, [%4];"
                 : "=r"(r0), "=r"(r1), "=r"(r2), "=r"(r3) : "r"(addr));
}
static __device__ __forceinline__ void mma_tf32(float& c0, float& c1, float& c2, float& c3,
                                                uint32_t a0, uint32_t a1, uint32_t a2, uint32_t a3,
                                                uint32_t b0, uint32_t b1) {
    asm volatile(
        "mma.sync.aligned.m16n8k8.row.col.f32.tf32.tf32.f32 "
        "{%0,%1,%2,%3}, {%4,%5,%6,%7}, {%8,%9}, {%0,%1,%2,%3};"
        : "+f"(c0), "+f"(c1), "+f"(c2), "+f"(c3)
        : "r"(a0), "r"(a1), "r"(a2), "r"(a3), "r"(b0), "r"(b1));
}

// ---------------- init / graph preprocessing ----------------
__global__ void k_zero_init() {
    int i = blockIdx.x * blockDim.x + threadIdx.x;
    if (i < Nn) { g_deg_out[i] = 0; g_deg_in[i] = 0; g_fill[i] = 0; }
    if (i < Dd) { g_bn_sum[i] = 0.f; g_bn_sq[i] = 0.f; }
}

__global__ void k_degrees(const int* __restrict__ src, const int* __restrict__ dst) {
    int e = blockIdx.x * blockDim.x + threadIdx.x;
    if (e >= Ee) return;
    atomicAdd(&g_deg_out[src[e]], 1);
    atomicAdd(&g_deg_in[dst[e]], 1);
}

__global__ void k_norms() {
    int i = blockIdx.x * blockDim.x + threadIdx.x;
    if (i >= Nn) return;
    int dout = g_deg_out[i]; if (dout < 1) dout = 1;
    int din  = g_deg_in[i];  if (din  < 1) din  = 1;
    g_norm_s[i] = rsqrtf((float)dout);
    g_norm_d[i] = rsqrtf((float)din);
}

#define SCAN_B 196
__global__ void k_scan1() {
    __shared__ int sh[256];
    int t = threadIdx.x, i = blockIdx.x * 256 + t;
    sh[t] = (i < Nn) ? g_deg_in[i] : 0;
    __syncthreads();
    for (int o = 128; o > 0; o >>= 1) { if (t < o) sh[t] += sh[t + o]; __syncthreads(); }
    if (t == 0) g_bsum[blockIdx.x] = sh[0];
}
__global__ void k_scan2() {
    __shared__ int sh[256];
    int t = threadIdx.x;
    int v = (t < SCAN_B) ? g_bsum[t] : 0;
    sh[t] = v;
    __syncthreads();
    for (int o = 1; o < 256; o <<= 1) {
        int x = (t >= o) ? sh[t - o] : 0;
        __syncthreads();
        sh[t] += x;
        __syncthreads();
    }
    g_boff[t] = sh[t] - v;
}
__global__ void k_scan3() {
    __shared__ int sh[256];
    int t = threadIdx.x, i = blockIdx.x * 256 + t;
    int v = (i < Nn) ? g_deg_in[i] : 0;
    sh[t] = v;
    __syncthreads();
    for (int o = 1; o < 256; o <<= 1) {
        int x = (t >= o) ? sh[t - o] : 0;
        __syncthreads();
        sh[t] += x;
        __syncthreads();
    }
    if (i < Nn) g_row_ptr[i] = g_boff[blockIdx.x] + sh[t] - v;
    if (blockIdx.x == 0 && t == 0) g_row_ptr[Nn] = Ee;
}

__global__ void k_fill(const int* __restrict__ src, const int* __restrict__ dst) {
    int e = blockIdx.x * blockDim.x + threadIdx.x;
    if (e >= Ee) return;
    int d = dst[e];
    int p = g_row_ptr[d] + atomicAdd(&g_fill[d], 1);
    g_col[p] = src[e];
}

// ---------------- transpose W [K,256] -> Wt [256,K], tf32-rounded ----------------
__global__ void k_transpose(const float* __restrict__ W, float* __restrict__ Wt, int K) {
    __shared__ float t[32][33];
    int c0 = blockIdx.x * 32;  // W col
    int r0 = blockIdx.y * 32;  // W row
    for (int i = threadIdx.y; i < 32; i += 8)
        t[i][threadIdx.x] = W[(size_t)(r0 + i) * Dd + c0 + threadIdx.x];
    __syncthreads();
    for (int i = threadIdx.y; i < 32; i += 8)
        Wt[(size_t)(c0 + i) * K + r0 + threadIdx.x] = tf32r(t[threadIdx.x][i]);
}

// ---------------- SpMM gather (tf32-rounded output) ----------------
__global__ void k_gather(const float* __restrict__ X, float* __restrict__ Mo) {
    int w = (blockIdx.x * blockDim.x + threadIdx.x) >> 5;
    int lane = threadIdx.x & 31;
    if (w >= Nn) return;
    int beg = g_row_ptr[w], end = g_row_ptr[w + 1];
    float4 a0 = make_float4(0.f, 0.f, 0.f, 0.f);
    float4 a1 = make_float4(0.f, 0.f, 0.f, 0.f);
    for (int e = beg; e < end; e++) {
        int s = g_col[e];
        float wt = g_norm_s[s];
        const float4* r = (const float4*)(X + (size_t)s * Dd);
        float4 v0 = r[lane];
        float4 v1 = r[lane + 32];
        a0.x += wt * v0.x; a0.y += wt * v0.y; a0.z += wt * v0.z; a0.w += wt * v0.w;
        a1.x += wt * v1.x; a1.y += wt * v1.y; a1.z += wt * v1.z; a1.w += wt * v1.w;
    }
    float wd = g_norm_d[w];
    a0.x = tf32r(a0.x * wd); a0.y = tf32r(a0.y * wd); a0.z = tf32r(a0.z * wd); a0.w = tf32r(a0.w * wd);
    a1.x = tf32r(a1.x * wd); a1.y = tf32r(a1.y * wd); a1.z = tf32r(a1.z * wd); a1.w = tf32r(a1.w * wd);
    float4* o = (float4*)(Mo + (size_t)w * Dd);
    o[lane] = a0;
    o[lane + 32] = a1;
}

// ---------------- tf32 mma.sync GEMM: C[M,256] = A[M,K] @ Bt^T + bias ----------------
// A [M,K] row-major fp32. Bt [256,K] row-major (W^T, tf32-rounded).
// CTA tile 128x128, BK=16, 8 warps, warp tile 32x64 (warp grid 4m x 2n).
#define TSTR 20            // smem row stride in floats (conflict-free for ldmatrix)
#define TILEW (128 * TSTR) // floats per tile buffer

template <int K>
__global__ __launch_bounds__(256) void gemm_mma(const float* __restrict__ A,
                                                const float* __restrict__ Bt,
                                                const float* __restrict__ bias,
                                                float* __restrict__ Cmat) {
    constexpr int CH = K / 16;
    __shared__ float As[2][TILEW];
    __shared__ float Bs[2][TILEW];

    const int tid = threadIdx.x;
    const int wid = tid >> 5, lane = tid & 31;
    const int mw = wid & 3, nw = wid >> 2;     // warp grid 4 x 2
    const int m0 = mw * 32, n0 = nw * 64;
    const int tileM = blockIdx.y * 128;
    const int colBase = blockIdx.x * 128;

    const uint32_t sA = smem_u32(As);
    const uint32_t sB = smem_u32(Bs);

    // loader indices: 512 float4 per tile, 2 per thread
    const int ldRow = tid >> 2;           // 0..63 (+64 for i=1)
    const int ldC4 = (tid & 3) * 4;

    auto load_tile = [&](int buf, int c) {
#pragma unroll
        for (int i = 0; i < 2; i++) {
            int row = ldRow + i * 64;
            int gr = tileM + row;
            uint32_t da = sA + (uint32_t)(buf * TILEW + row * TSTR + ldC4) * 4;
            cp_async16(da, A + (size_t)gr * K + c * 16 + ldC4, (gr < Nn) ? 16 : 0);
        }
#pragma unroll
        for (int i = 0; i < 2; i++) {
            int row = ldRow + i * 64;
            uint32_t db = sB + (uint32_t)(buf * TILEW + row * TSTR + ldC4) * 4;
            cp_async16(db, Bt + (size_t)(colBase + row) * K + c * 16 + ldC4, 16);
        }
        asm volatile("cp.async.commit_group;" ::: "memory");
    };

    float acc[2][8][4];
#pragma unroll
    for (int mt = 0; mt < 2; mt++)
#pragma unroll
        for (int nt = 0; nt < 8; nt++)
#pragma unroll
            for (int q = 0; q < 4; q++) acc[mt][nt][q] = 0.f;

    load_tile(0, 0);

    const int matid = lane >> 3;
    const int mrow = lane & 7;

    for (int c = 0; c < CH; c++) {
        int buf = c & 1;
        if (c + 1 < CH) {
            load_tile(buf ^ 1, c + 1);
            asm volatile("cp.async.wait_group 1;" ::: "memory");
        } else {
            asm volatile("cp.async.wait_group 0;" ::: "memory");
        }
        __syncthreads();

#pragma unroll
        for (int kk = 0; kk < 16; kk += 8) {
            // A fragments: 2 m16 tiles
            uint32_t a[2][4];
#pragma unroll
            for (int mt = 0; mt < 2; mt++) {
                int row = m0 + mt * 16 + (matid & 1) * 8 + mrow;
                int col = kk + (matid >> 1) * 4;
                uint32_t addr = sA + (uint32_t)(buf * TILEW + row * TSTR + col) * 4;
                ldsm4(a[mt][0], a[mt][1], a[mt][2], a[mt][3], addr);
#pragma unroll
                for (int j = 0; j < 4; j++) a[mt][j] = tf32u(a[mt][j]);
            }
            // B fragments: 8 n8 tiles via 4 ldmatrix.x4
            uint32_t b[4][4];
#pragma unroll
            for (int bt = 0; bt < 4; bt++) {
                int n = n0 + bt * 16 + (matid >> 1) * 8 + mrow;
                int col = kk + (matid & 1) * 4;
                uint32_t addr = sB + (uint32_t)(buf * TILEW + n * TSTR + col) * 4;
                ldsm4(b[bt][0], b[bt][1], b[bt][2], b[bt][3], addr);
            }
#pragma unroll
            for (int mt = 0; mt < 2; mt++)
#pragma unroll
                for (int nt = 0; nt < 8; nt++) {
                    uint32_t b0 = b[nt >> 1][(nt & 1) * 2 + 0];
                    uint32_t b1 = b[nt >> 1][(nt & 1) * 2 + 1];
                    mma_tf32(acc[mt][nt][0], acc[mt][nt][1], acc[mt][nt][2], acc[mt][nt][3],
                             a[mt][0], a[mt][1], a[mt][2], a[mt][3], b0, b1);
                }
        }
        __syncthreads();
    }

    // epilogue
    const int rq = lane >> 2;          // 0..7
    const int cq = (lane & 3) * 2;     // 0,2,4,6
#pragma unroll
    for (int mt = 0; mt < 2; mt++) {
        int rowA = tileM + m0 + mt * 16 + rq;
        int rowB = rowA + 8;
#pragma unroll
        for (int nt = 0; nt < 8; nt++) {
            int col = colBase + n0 + nt * 8 + cq;
            float bv0 = bias[col], bv1 = bias[col + 1];
            if (rowA < Nn) {
                float2 v = make_float2(acc[mt][nt][0] + bv0, acc[mt][nt][1] + bv1);
                *(float2*)(Cmat + (size_t)rowA * Dd + col) = v;
            }
            if (rowB < Nn) {
                float2 v = make_float2(acc[mt][nt][2] + bv0, acc[mt][nt][3] + bv1);
                *(float2*)(Cmat + (size_t)rowB * Dd + col) = v;
            }
        }
    }
}

// ---------------- batchnorm ----------------
#define BN_BLOCKS 200
#define BN_ROWS 250

__global__ void k_bn_stats(const float* __restrict__ X) {
    int c = threadIdx.x;
    int r0 = blockIdx.x * BN_ROWS;
    float s = 0.f, q = 0.f;
    for (int i = 0; i < BN_ROWS; i++) {
        int r = r0 + i;
        if (r < Nn) {
            float v = X[(size_t)r * Dd + c];
            s += v;
            q += v * v;
        }
    }
    atomicAdd(&g_bn_sum[c], s);
    atomicAdd(&g_bn_sq[c], q);
}

__global__ void k_bn_finalize(const float* __restrict__ gamma, const float* __restrict__ beta) {
    int c = threadIdx.x;
    if (c >= Dd) return;
    float mu = g_bn_sum[c] / (float)Nn;
    float var = g_bn_sq[c] / (float)Nn - mu * mu;
    float inv = rsqrtf(var + 1e-5f);
    float sc = gamma[c] * inv;
    g_bn_scale[c] = sc;
    g_bn_shift[c] = beta[c] - mu * sc;
    g_bn_sum[c] = 0.f;
    g_bn_sq[c] = 0.f;
}

__global__ void k_bn_apply_elu(float* __restrict__ X) {
    int i = blockIdx.x * blockDim.x + threadIdx.x;
    if (i >= Nn * Dd) return;
    int c = i & (Dd - 1);
    float y = g_bn_scale[c] * X[i] + g_bn_shift[c];
    X[i] = (y > 0.f) ? y : expm1f(y);
}

// ---------------- logits: out[N,40] = X[N,256] @ W[256,40] + b ----------------
__global__ __launch_bounds__(256) void k_logits(const float* __restrict__ X, const float* __restrict__ W,
                                                const float* __restrict__ b, float* __restrict__ out) {
    __shared__ float sw[Dd * Cc];
    int tid = threadIdx.x;
    for (int i = tid; i < Dd * Cc; i += 256) sw[i] = W[i];
    __syncthreads();
    int grp = tid & 7;       // k-slice 0..7
    int rloc = tid >> 3;     // 0..31
    int row = blockIdx.x * 32 + rloc;
    float acc[Cc];
#pragma unroll
    for (int c = 0; c < Cc; c++) acc[c] = 0.f;
    if (row < Nn) {
        const float* xr = X + (size_t)row * Dd + grp * 32;
#pragma unroll 8
        for (int k = 0; k < 32; k++) {
            float xv = xr[k];
            const float* wr = &sw[(grp * 32 + k) * Cc];
#pragma unroll
            for (int c = 0; c < Cc; c++) acc[c] += xv * wr[c];
        }
    }
#pragma unroll
    for (int o = 4; o > 0; o >>= 1)
#pragma unroll
        for (int c = 0; c < Cc; c++)
            acc[c] += __shfl_down_sync(0xFFFFFFFF, acc[c], o);
    if (grp == 0 && row < Nn) {
        float* op = out + (size_t)row * Cc;
#pragma unroll
        for (int c = 0; c < Cc; c++) op[c] = acc[c] + b[c];
    }
}

// ---------------- host orchestration ----------------
extern "C" void kernel_launch(void* const* d_in, const int* in_sizes, int n_in,
                              void* d_out, int out_size) {
    const float* feat  = (const float*)d_in[0];
    const int*   src   = (const int*)d_in[1];
    const int*   dst   = (const int*)d_in[2];
    const float* W_fc  = (const float*)d_in[3];
    const float* b_fc  = (const float*)d_in[4];
    const float* W1    = (const float*)d_in[5];
    const float* b1    = (const float*)d_in[6];
    const float* W2    = (const float*)d_in[7];
    const float* b2    = (const float*)d_in[8];
    const float* W3    = (const float*)d_in[9];
    const float* b3    = (const float*)d_in[10];
    const float* gamma = (const float*)d_in[11];
    const float* beta  = (const float*)d_in[12];
    const float* W_lin = (const float*)d_in[13];
    const float* b_lin = (const float*)d_in[14];
    float* out = (float*)d_out;

    float *pX, *pM, *pY, *pWtFc, *pWt1, *pWt2, *pWt3;
    cudaGetSymbolAddress((void**)&pX, g_X);
    cudaGetSymbolAddress((void**)&pM, g_M);
    cudaGetSymbolAddress((void**)&pY, g_Y);
    cudaGetSymbolAddress((void**)&pWtFc, g_WtFc);
    cudaGetSymbolAddress((void**)&pWt1, g_Wt1);
    cudaGetSymbolAddress((void**)&pWt2, g_Wt2);
    cudaGetSymbolAddress((void**)&pWt3, g_Wt3);

    const int T = 256;
    dim3 gemmGrid(2, (Nn + 127) / 128);        // x = N tile (2x128), y = M tile
    const int gatherBlocks = (Nn * 32 + T - 1) / T;
    const int ewBlocks = (Nn * Dd + T - 1) / T;

    // graph preprocessing
    k_zero_init<<<(Nn + T - 1) / T, T>>>();
    k_degrees<<<(Ee + T - 1) / T, T>>>(src, dst);
    k_norms<<<(Nn + T - 1) / T, T>>>();
    k_scan1<<<SCAN_B, 256>>>();
    k_scan2<<<1, 256>>>();
    k_scan3<<<SCAN_B, 256>>>();
    k_fill<<<(Ee + T - 1) / T, T>>>(src, dst);

    // weight transposes (tf32-rounded)
    k_transpose<<<dim3(Dd / 32, Ff / 32), dim3(32, 8)>>>(W_fc, pWtFc, Ff);
    k_transpose<<<dim3(Dd / 32, Dd / 32), dim3(32, 8)>>>(W1, pWt1, Dd);
    k_transpose<<<dim3(Dd / 32, Dd / 32), dim3(32, 8)>>>(W2, pWt2, Dd);
    k_transpose<<<dim3(Dd / 32, Dd / 32), dim3(32, 8)>>>(W3, pWt3, Dd);

    // x = feat @ W_fc + b_fc
    gemm_mma<Ff><<<gemmGrid, 256>>>(feat, pWtFc, b_fc, pX);

    // layer 1
    k_gather<<<gatherBlocks, T>>>(pX, pM);
    gemm_mma<Dd><<<gemmGrid, 256>>>(pM, pWt1, b1, pY);
    k_bn_stats<<<BN_BLOCKS, Dd>>>(pY);
    k_bn_finalize<<<1, Dd>>>(gamma, beta);
    k_bn_apply_elu<<<ewBlocks, T>>>(pY);

    // layer 2
    k_gather<<<gatherBlocks, T>>>(pY, pM);
    gemm_mma<Dd><<<gemmGrid, 256>>>(pM, pWt2, b2, pX);
    k_bn_stats<<<BN_BLOCKS, Dd>>>(pX);
    k_bn_finalize<<<1, Dd>>>(gamma, beta);
    k_bn_apply_elu<<<ewBlocks, T>>>(pX);

    // layer 3 -> node embeddings into output
    k_gather<<<gatherBlocks, T>>>(pX, pM);
    gemm_mma<Dd><<<gemmGrid, 256>>>(pM, pWt3, b3, out);

    // logits
    k_logits<<<(Nn + 31) / 32, 256>>>(out, W_lin, b_lin, out + (size_t)Nn * Dd);
}